// round 1
// baseline (speedup 1.0000x reference)
#include <cuda_runtime.h>
#include <math.h>

// Problem constants
#define BB 512
#define TT 168
#define II 64
#define HH 256
#define GG 1024   // 4*H
#define BT (BB*TT)

// ---------------------------------------------------------------------------
// Scratch (device globals: allocation-free rule)
// ---------------------------------------------------------------------------
__device__ float g_gx[(size_t)BT * GG];   // gate pre-activations, interleaved gate layout (352 MB)
__device__ float g_out1[(size_t)BT * HH]; // layer-1 hidden outputs (88 MB)
__device__ float g_WT[HH * GG];           // W_ih transposed+interleaved: [k][j*4+q]
__device__ float g_Whh[HH * GG];          // W_hh transposed+interleaved: [k][j*4+q]
__device__ float g_bias[GG];              // b_ih+b_hh, interleaved

// Interleaving: column n = j*4+q  maps to raw gate row r = q*256 + j
// (q: 0=i, 1=f, 2=g, 3=o). Thread `tid` in the scan owns h-column j=tid and
// reads its 4 gate weights with ONE float4 load per k.

// ---------------------------------------------------------------------------
// Weight prep: transpose + gate-interleave + bias combine
// ---------------------------------------------------------------------------
__global__ void prep_weights(const float* __restrict__ W_ih,
                             const float* __restrict__ W_hh,
                             const float* __restrict__ b_ih,
                             const float* __restrict__ b_hh,
                             int K)
{
    int idx = blockIdx.x * 256 + threadIdx.x;  // 0 .. 256*1024-1
    int n = idx & (GG - 1);
    int k = idx >> 10;
    int j = n >> 2;
    int q = n & 3;
    int r = q * HH + j;
    if (k < K) g_WT[k * GG + n] = W_ih[r * K + k];
    g_Whh[k * GG + n] = W_hh[r * HH + k];
    if (k == 0) g_bias[n] = b_ih[r] + b_hh[r];
}

// ---------------------------------------------------------------------------
// Feed-forward GEMM: g_gx[M=BT][N=1024] = X[M][K] * g_WT[K][N] + g_bias
// Tiled 64x64x16, 256 threads, 4x4 register blocking. All dims divide exactly.
// ---------------------------------------------------------------------------
template <int K>
__global__ __launch_bounds__(256)
void gemm_gx(const float* __restrict__ X_in)
{
    const float* X = X_in ? X_in : (const float*)g_out1;

    __shared__ float As[16][68];  // [k][m], padded to reduce store conflicts
    __shared__ float Bs[16][64];  // [k][n]

    const int tid = threadIdx.x;
    const int m0 = blockIdx.x * 64;
    const int n0 = blockIdx.y * 64;
    const int tm = (tid >> 4) << 2;   // 0..60
    const int tn = (tid & 15) << 2;   // 0..60
    const int lm = tid >> 2;          // 0..63  (A load row)
    const int lk = (tid & 3) << 2;    // 0,4,8,12 (A load k)
    const int bk = tid >> 4;          // 0..15  (B load k)
    const int bn = (tid & 15) << 2;   // 0..60  (B load n)

    float acc[4][4] = {};

    for (int k0 = 0; k0 < K; k0 += 16) {
        float4 av = *(const float4*)(X + (size_t)(m0 + lm) * K + k0 + lk);
        As[lk + 0][lm] = av.x;
        As[lk + 1][lm] = av.y;
        As[lk + 2][lm] = av.z;
        As[lk + 3][lm] = av.w;
        *(float4*)&Bs[bk][bn] = *(const float4*)(g_WT + (size_t)(k0 + bk) * GG + n0 + bn);
        __syncthreads();

#pragma unroll
        for (int k = 0; k < 16; k++) {
            float a[4], b[4];
            *(float4*)a = *(const float4*)&As[k][tm];
            *(float4*)b = *(const float4*)&Bs[k][tn];
#pragma unroll
            for (int i = 0; i < 4; i++)
#pragma unroll
                for (int j = 0; j < 4; j++)
                    acc[i][j] += a[i] * b[j];
        }
        __syncthreads();
    }

    float4 bias = *(const float4*)(g_bias + n0 + tn);
#pragma unroll
    for (int i = 0; i < 4; i++) {
        float4 r;
        r.x = acc[i][0] + bias.x;
        r.y = acc[i][1] + bias.y;
        r.z = acc[i][2] + bias.z;
        r.w = acc[i][3] + bias.w;
        *(float4*)(g_gx + (size_t)(m0 + tm + i) * GG + n0 + tn) = r;
    }
}

// ---------------------------------------------------------------------------
// Recurrent scan. Each CTA owns MB=4 batch rows, loops over all T steps.
// Batch rows are independent -> no inter-CTA sync. h lives in SMEM (broadcast
// reads), c lives in registers (thread tid owns h-column tid for all 4 rows).
// Per step: g[4][1024] = gx + h @ W_hhT, gate-interleaved so one float4 W load
// per k serves all 4 gates of a column.
// ---------------------------------------------------------------------------
__global__ __launch_bounds__(256)
void lstm_scan(float* __restrict__ out_in)
{
    float* out = out_in ? out_in : (float*)g_out1;

    __shared__ float sh_h[4][HH];
    const int tid = threadIdx.x;     // 0..255 == h column index
    const int b0 = blockIdx.x * 4;

    float c[4] = {0.f, 0.f, 0.f, 0.f};
#pragma unroll
    for (int mb = 0; mb < 4; mb++) sh_h[mb][tid] = 0.f;
    __syncthreads();

    const float4* __restrict__ W4 = (const float4*)g_Whh;  // [k][256] float4s

    for (int t = 0; t < TT; t++) {
        float4 acc[4];
#pragma unroll
        for (int mb = 0; mb < 4; mb++)
            acc[mb] = *(const float4*)(g_gx + ((size_t)(b0 + mb) * TT + t) * GG + tid * 4);

#pragma unroll 8
        for (int k = 0; k < HH; k++) {
            float4 w = W4[k * (GG / 4) + tid];
#pragma unroll
            for (int mb = 0; mb < 4; mb++) {
                float hk = sh_h[mb][k];
                acc[mb].x += hk * w.x;
                acc[mb].y += hk * w.y;
                acc[mb].z += hk * w.z;
                acc[mb].w += hk * w.w;
            }
        }

        __syncthreads();  // everyone done reading sh_h for this step
#pragma unroll
        for (int mb = 0; mb < 4; mb++) {
            float ig = 1.f / (1.f + __expf(-acc[mb].x));
            float fg = 1.f / (1.f + __expf(-acc[mb].y));
            float gg = tanhf(acc[mb].z);
            float og = 1.f / (1.f + __expf(-acc[mb].w));
            float cn = fg * c[mb] + ig * gg;
            c[mb] = cn;
            float h = og * tanhf(cn);
            sh_h[mb][tid] = h;
            out[((size_t)(b0 + mb) * TT + t) * HH + tid] = h;
        }
        __syncthreads();  // new h visible before next step's reads
    }
}

// ---------------------------------------------------------------------------
// Launch
// ---------------------------------------------------------------------------
extern "C" void kernel_launch(void* const* d_in, const int* in_sizes, int n_in,
                              void* d_out, int out_size)
{
    const float* x     = (const float*)d_in[0];
    const float* W_ih1 = (const float*)d_in[1];
    const float* W_hh1 = (const float*)d_in[2];
    const float* b_ih1 = (const float*)d_in[3];
    const float* b_hh1 = (const float*)d_in[4];
    const float* W_ih2 = (const float*)d_in[5];
    const float* W_hh2 = (const float*)d_in[6];
    const float* b_ih2 = (const float*)d_in[7];
    const float* b_hh2 = (const float*)d_in[8];
    float* out = (float*)d_out;

    dim3 ggrid(BT / 64, GG / 64);  // 1344 x 16

    // Layer 1
    prep_weights<<<1024, 256>>>(W_ih1, W_hh1, b_ih1, b_hh1, II);
    gemm_gx<II><<<ggrid, 256>>>(x);
    lstm_scan<<<BB / 4, 256>>>(nullptr);        // writes g_out1

    // Layer 2
    prep_weights<<<1024, 256>>>(W_ih2, W_hh2, b_ih2, b_hh2, HH);
    gemm_gx<HH><<<ggrid, 256>>>(nullptr);       // reads g_out1
    lstm_scan<<<BB / 4, 256>>>(out);            // writes final output
}

// round 2
// speedup vs baseline: 1.0372x; 1.0372x over previous
#include <cuda_runtime.h>
#include <math.h>
#include <stdint.h>

// Problem constants
#define BB 512
#define TT 168
#define II 64
#define HH 256
#define GG 1024   // 4*H
#define BT (BB*TT)

// ---------------------------------------------------------------------------
// Scratch (device globals: allocation-free rule)
// ---------------------------------------------------------------------------
__device__ float g_gx[(size_t)BT * GG];   // gate pre-activations, interleaved gate layout
__device__ float g_out1[(size_t)BT * HH]; // layer-1 hidden outputs
__device__ float g_WT[HH * GG];           // W_ih transposed+interleaved: [k][j*4+q]
__device__ float g_Whh[HH * GG];          // W_hh transposed+interleaved: [k][j*4+q]
__device__ float g_bias[GG];              // b_ih+b_hh, interleaved

// Interleaving: column n = j*4+q maps to raw gate row r = q*256 + j
// (q: 0=i, 1=f, 2=g, 3=o).

// ---------------------------------------------------------------------------
// Weight prep: transpose + gate-interleave + bias combine
// ---------------------------------------------------------------------------
__global__ void prep_weights(const float* __restrict__ W_ih,
                             const float* __restrict__ W_hh,
                             const float* __restrict__ b_ih,
                             const float* __restrict__ b_hh,
                             int K)
{
    int idx = blockIdx.x * 256 + threadIdx.x;  // 0 .. 256*1024-1
    int n = idx & (GG - 1);
    int k = idx >> 10;
    int j = n >> 2;
    int q = n & 3;
    int r = q * HH + j;
    if (k < K) g_WT[k * GG + n] = W_ih[r * K + k];
    g_Whh[k * GG + n] = W_hh[r * HH + k];
    if (k == 0) g_bias[n] = b_ih[r] + b_hh[r];
}

// ---------------------------------------------------------------------------
// tf32 helpers
// ---------------------------------------------------------------------------
__device__ __forceinline__ uint32_t f2tf32(float x) {
    uint32_t r;
    asm("cvt.rna.tf32.f32 %0, %1;" : "=r"(r) : "f"(x));
    return r;
}

__device__ __forceinline__ void mma_tf32(float* c, const uint32_t* a, const uint32_t* b) {
    asm volatile(
        "mma.sync.aligned.m16n8k8.row.col.f32.tf32.tf32.f32 "
        "{%0,%1,%2,%3}, {%4,%5,%6,%7}, {%8,%9}, {%0,%1,%2,%3};"
        : "+f"(c[0]), "+f"(c[1]), "+f"(c[2]), "+f"(c[3])
        : "r"(a[0]), "r"(a[1]), "r"(a[2]), "r"(a[3]), "r"(b[0]), "r"(b[1]));
}

// ---------------------------------------------------------------------------
// Feed-forward GEMM (tensor cores, tf32):
//   g_gx[M=BT][N=1024] = X[M][K] * g_WT[K][N] + g_bias
// CTA tile 128(M) x 64(N), k-tile 32, double-buffered SMEM.
// 8 warps in 4x2 layout, each warp 32x32 (2 m16 x 4 n8 mma tiles).
// SMEM tiles are stored PRE-PERMUTED into mma fragment order:
//   A: [kblk(4)][mblk(8)][lane(32)][frag(4)]  -> one LDS.128 per A fragment
//   B: [kblk(4)][nblk(8)][lane(32)][frag(2)]  -> one LDS.64  per B fragment
// ---------------------------------------------------------------------------
template <int K>
__global__ __launch_bounds__(256)
void gemm_gx_tf32(const float* __restrict__ X_in)
{
    const float* X = X_in ? X_in : (const float*)g_out1;
    constexpr int KT = K / 32;

    __shared__ uint32_t sA[2][4096];  // 128x32 permuted
    __shared__ uint32_t sB[2][2048];  // 32x64 permuted

    const int tid  = threadIdx.x;
    const int warp = tid >> 5;
    const int lane = tid & 31;
    const int m0 = blockIdx.x * 128;
    const int n0 = blockIdx.y * 64;
    const int wmb = (warp >> 1) * 2;  // warp's first m16 block (0,2,4,6)
    const int wnb = (warp & 1) * 4;   // warp's first n8 block (0,4)

    float acc[2][4][4];
#pragma unroll
    for (int i = 0; i < 2; i++)
#pragma unroll
        for (int j = 0; j < 4; j++)
#pragma unroll
            for (int q = 0; q < 4; q++) acc[i][j][q] = 0.f;

    float4 av[4];
    float4 bv[2];

    // ---- global load of k-tile kt into registers ----
    auto ldg_tile = [&](int kt) {
#pragma unroll
        for (int i = 0; i < 4; i++) {
            int v = tid + 256 * i;          // 0..1023
            int row = v >> 3;               // 0..127
            int kc = (v & 7) * 4;           // 0..28
            av[i] = *(const float4*)(X + (size_t)(m0 + row) * K + kt * 32 + kc);
        }
#pragma unroll
        for (int i = 0; i < 2; i++) {
            int v = tid + 256 * i;          // 0..511
            int row = v >> 4;               // 0..31
            int nc = (v & 15) * 4;          // 0..60
            bv[i] = *(const float4*)(g_WT + (size_t)(kt * 32 + row) * GG + n0 + nc);
        }
    };

    // ---- permuted store of registers into SMEM buffer ----
    auto sts_tile = [&](int buf) {
#pragma unroll
        for (int i = 0; i < 4; i++) {
            int v = tid + 256 * i;
            int row = v >> 3;
            int kc0 = (v & 7) * 4;
            int mblk = row >> 4, mr = row & 15;
            float f[4] = {av[i].x, av[i].y, av[i].z, av[i].w};
#pragma unroll
            for (int j = 0; j < 4; j++) {
                int kc = kc0 + j;
                int kblk = kc >> 3, kin = kc & 7;
                int t = ((mr & 7) << 2) | (kin & 3);
                int slot = ((kin >> 2) << 1) | (mr >> 3);
                sA[buf][(((kblk << 3) | mblk) << 7) + (t << 2) + slot] = f2tf32(f[j]);
            }
        }
#pragma unroll
        for (int i = 0; i < 2; i++) {
            int v = tid + 256 * i;
            int row = v >> 4;               // k within tile
            int nc0 = (v & 15) * 4;
            int kblk = row >> 3, kin = row & 7;
            float f[4] = {bv[i].x, bv[i].y, bv[i].z, bv[i].w};
#pragma unroll
            for (int j = 0; j < 4; j++) {
                int nc = nc0 + j;
                int nblk = nc >> 3, nin = nc & 7;
                int t = (nin << 2) | (kin & 3);
                int slot = kin >> 2;
                sB[buf][(((kblk << 3) | nblk) << 6) + (t << 1) + slot] = f2tf32(f[j]);
            }
        }
    };

    // ---- compute one k-tile from SMEM buffer ----
    auto compute = [&](int buf) {
#pragma unroll
        for (int ks = 0; ks < 4; ks++) {
            uint32_t afr[2][4];
            uint32_t bfr[4][2];
#pragma unroll
            for (int mi = 0; mi < 2; mi++) {
                uint4 a = *(const uint4*)&sA[buf][(((ks << 3) | (wmb + mi)) << 7) + (lane << 2)];
                afr[mi][0] = a.x; afr[mi][1] = a.y; afr[mi][2] = a.z; afr[mi][3] = a.w;
            }
#pragma unroll
            for (int ni = 0; ni < 4; ni++) {
                uint2 b = *(const uint2*)&sB[buf][(((ks << 3) | (wnb + ni)) << 6) + (lane << 1)];
                bfr[ni][0] = b.x; bfr[ni][1] = b.y;
            }
#pragma unroll
            for (int mi = 0; mi < 2; mi++)
#pragma unroll
                for (int ni = 0; ni < 4; ni++)
                    mma_tf32(acc[mi][ni], afr[mi], bfr[ni]);
        }
    };

    // ---- pipelined mainloop ----
    ldg_tile(0);
    sts_tile(0);
    __syncthreads();
#pragma unroll
    for (int kt = 0; kt < KT; kt++) {
        if (kt + 1 < KT) ldg_tile(kt + 1);
        compute(kt & 1);
        if (kt + 1 < KT) sts_tile((kt + 1) & 1);
        __syncthreads();
    }

    // ---- epilogue: add bias, write fp32 ----
    const int g = lane >> 2;          // 0..7
    const int cq = lane & 3;          // 0..3
#pragma unroll
    for (int ni = 0; ni < 4; ni++) {
        int gn = n0 + ((wnb + ni) << 3) + cq * 2;
        float bx = g_bias[gn];
        float by = g_bias[gn + 1];
#pragma unroll
        for (int mi = 0; mi < 2; mi++) {
            int gm = m0 + ((wmb + mi) << 4) + g;
            float2 r0 = make_float2(acc[mi][ni][0] + bx, acc[mi][ni][1] + by);
            float2 r1 = make_float2(acc[mi][ni][2] + bx, acc[mi][ni][3] + by);
            *(float2*)(g_gx + (size_t)gm * GG + gn) = r0;
            *(float2*)(g_gx + (size_t)(gm + 8) * GG + gn) = r1;
        }
    }
}

// ---------------------------------------------------------------------------
// Recurrent scan. Each CTA owns MB=4 batch rows, loops over all T steps.
// h in SMEM (broadcast reads), c in registers. Gate-interleaved W so one
// float4 load per k serves all 4 gates of a column. (fp32; unchanged from R1)
// ---------------------------------------------------------------------------
__global__ __launch_bounds__(256)
void lstm_scan(float* __restrict__ out_in)
{
    float* out = out_in ? out_in : (float*)g_out1;

    __shared__ float sh_h[4][HH];
    const int tid = threadIdx.x;     // h column index
    const int b0 = blockIdx.x * 4;

    float c[4] = {0.f, 0.f, 0.f, 0.f};
#pragma unroll
    for (int mb = 0; mb < 4; mb++) sh_h[mb][tid] = 0.f;
    __syncthreads();

    const float4* __restrict__ W4 = (const float4*)g_Whh;

    for (int t = 0; t < TT; t++) {
        float4 acc[4];
#pragma unroll
        for (int mb = 0; mb < 4; mb++)
            acc[mb] = *(const float4*)(g_gx + ((size_t)(b0 + mb) * TT + t) * GG + tid * 4);

#pragma unroll 8
        for (int k = 0; k < HH; k++) {
            float4 w = W4[k * (GG / 4) + tid];
#pragma unroll
            for (int mb = 0; mb < 4; mb++) {
                float hk = sh_h[mb][k];
                acc[mb].x += hk * w.x;
                acc[mb].y += hk * w.y;
                acc[mb].z += hk * w.z;
                acc[mb].w += hk * w.w;
            }
        }

        __syncthreads();
#pragma unroll
        for (int mb = 0; mb < 4; mb++) {
            float ig = 1.f / (1.f + __expf(-acc[mb].x));
            float fg = 1.f / (1.f + __expf(-acc[mb].y));
            float gg = tanhf(acc[mb].z);
            float og = 1.f / (1.f + __expf(-acc[mb].w));
            float cn = fg * c[mb] + ig * gg;
            c[mb] = cn;
            float h = og * tanhf(cn);
            sh_h[mb][tid] = h;
            out[((size_t)(b0 + mb) * TT + t) * HH + tid] = h;
        }
        __syncthreads();
    }
}

// ---------------------------------------------------------------------------
// Launch
// ---------------------------------------------------------------------------
extern "C" void kernel_launch(void* const* d_in, const int* in_sizes, int n_in,
                              void* d_out, int out_size)
{
    const float* x     = (const float*)d_in[0];
    const float* W_ih1 = (const float*)d_in[1];
    const float* W_hh1 = (const float*)d_in[2];
    const float* b_ih1 = (const float*)d_in[3];
    const float* b_hh1 = (const float*)d_in[4];
    const float* W_ih2 = (const float*)d_in[5];
    const float* W_hh2 = (const float*)d_in[6];
    const float* b_ih2 = (const float*)d_in[7];
    const float* b_hh2 = (const float*)d_in[8];
    float* out = (float*)d_out;

    dim3 ggrid(BT / 128, GG / 64);  // 672 x 16

    // Layer 1
    prep_weights<<<1024, 256>>>(W_ih1, W_hh1, b_ih1, b_hh1, II);
    gemm_gx_tf32<II><<<ggrid, 256>>>(x);
    lstm_scan<<<BB / 4, 256>>>(nullptr);        // writes g_out1

    // Layer 2
    prep_weights<<<1024, 256>>>(W_ih2, W_hh2, b_ih2, b_hh2, HH);
    gemm_gx_tf32<HH><<<ggrid, 256>>>(nullptr);  // reads g_out1
    lstm_scan<<<BB / 4, 256>>>(out);            // writes final output
}

// round 3
// speedup vs baseline: 1.2565x; 1.2114x over previous
#include <cuda_runtime.h>
#include <math.h>
#include <stdint.h>

// Problem constants
#define BB 512
#define TT 168
#define II 64
#define HH 256
#define GG 1024   // 4*H
#define BT (BB*TT)

#define GXS 1032  // padded row stride (floats) for scan smem gx/gates buffer

// ---------------------------------------------------------------------------
// Scratch (device globals: allocation-free rule)
// ---------------------------------------------------------------------------
__device__ float g_gx[(size_t)BT * GG];   // gate pre-activations, interleaved gate layout
__device__ float g_out1[(size_t)BT * HH]; // layer-1 hidden outputs
__device__ float g_WT[HH * GG];           // W_ih transposed+interleaved (GEMM B)
__device__ uint32_t g_WhhP[HH * GG];      // W_hh permuted tf32, mma B-fragment order
__device__ float g_bias[GG];              // b_ih+b_hh, interleaved

// Interleaving: column n = j*4+q maps to raw gate row r = q*256 + j
// (q: 0=i, 1=f, 2=g, 3=o).

// ---------------------------------------------------------------------------
// tf32 helpers
// ---------------------------------------------------------------------------
__device__ __forceinline__ uint32_t f2tf32(float x) {
    uint32_t r;
    asm("cvt.rna.tf32.f32 %0, %1;" : "=r"(r) : "f"(x));
    return r;
}

__device__ __forceinline__ void mma_tf32(float* c, const uint32_t* a, const uint32_t* b) {
    asm volatile(
        "mma.sync.aligned.m16n8k8.row.col.f32.tf32.tf32.f32 "
        "{%0,%1,%2,%3}, {%4,%5,%6,%7}, {%8,%9}, {%0,%1,%2,%3};"
        : "+f"(c[0]), "+f"(c[1]), "+f"(c[2]), "+f"(c[3])
        : "r"(a[0]), "r"(a[1]), "r"(a[2]), "r"(a[3]), "r"(b[0]), "r"(b[1]));
}

// ---------------------------------------------------------------------------
// Weight prep: transpose + gate-interleave + bias combine + scan-mma permute
// ---------------------------------------------------------------------------
__global__ void prep_weights(const float* __restrict__ W_ih,
                             const float* __restrict__ W_hh,
                             const float* __restrict__ b_ih,
                             const float* __restrict__ b_hh,
                             int K)
{
    int idx = blockIdx.x * 256 + threadIdx.x;  // 0 .. 256*1024-1
    int n = idx & (GG - 1);
    int k = idx >> 10;
    int j = n >> 2;
    int q = n & 3;
    int r = q * HH + j;
    if (k < K) g_WT[k * GG + n] = W_ih[r * K + k];

    // scan W: B-fragment permuted tf32.
    // m16n8k8 B frag: lane=(nin<<2)|(kin&3), slot=kin>>2 (b0=B[k=c][n=g], b1=B[k=c+4][n=g])
    // Pack 2 consecutive kblks per 16B: uint4 element = [kblk even: slot0,slot1 | kblk odd: slot0,slot1]
    {
        float w = W_hh[r * HH + k];
        int nblk = n >> 3, nin = n & 7;
        int kblk = k >> 3, kin = k & 7;
        int lane = (nin << 2) | (kin & 3);
        int slot = kin >> 2;
        int kpair = kblk >> 1, kodd = kblk & 1;
        g_WhhP[((((nblk * 16 + kpair) * 32) + lane) << 2) + (kodd << 1) + slot] = f2tf32(w);
    }
    if (k == 0) g_bias[n] = b_ih[r] + b_hh[r];
}

// ---------------------------------------------------------------------------
// Feed-forward GEMM (tensor cores, tf32):
//   g_gx[M=BT][N=1024] = X[M][K] * g_WT[K][N] + g_bias   (unchanged from R2)
// ---------------------------------------------------------------------------
template <int K>
__global__ __launch_bounds__(256)
void gemm_gx_tf32(const float* __restrict__ X_in)
{
    const float* X = X_in ? X_in : (const float*)g_out1;
    constexpr int KT = K / 32;

    __shared__ uint32_t sA[2][4096];  // 128x32 permuted
    __shared__ uint32_t sB[2][2048];  // 32x64 permuted

    const int tid  = threadIdx.x;
    const int warp = tid >> 5;
    const int lane = tid & 31;
    const int m0 = blockIdx.x * 128;
    const int n0 = blockIdx.y * 64;
    const int wmb = (warp >> 1) * 2;
    const int wnb = (warp & 1) * 4;

    float acc[2][4][4];
#pragma unroll
    for (int i = 0; i < 2; i++)
#pragma unroll
        for (int j = 0; j < 4; j++)
#pragma unroll
            for (int q = 0; q < 4; q++) acc[i][j][q] = 0.f;

    float4 av[4];
    float4 bv[2];

    auto ldg_tile = [&](int kt) {
#pragma unroll
        for (int i = 0; i < 4; i++) {
            int v = tid + 256 * i;
            int row = v >> 3;
            int kc = (v & 7) * 4;
            av[i] = *(const float4*)(X + (size_t)(m0 + row) * K + kt * 32 + kc);
        }
#pragma unroll
        for (int i = 0; i < 2; i++) {
            int v = tid + 256 * i;
            int row = v >> 4;
            int nc = (v & 15) * 4;
            bv[i] = *(const float4*)(g_WT + (size_t)(kt * 32 + row) * GG + n0 + nc);
        }
    };

    auto sts_tile = [&](int buf) {
#pragma unroll
        for (int i = 0; i < 4; i++) {
            int v = tid + 256 * i;
            int row = v >> 3;
            int kc0 = (v & 7) * 4;
            int mblk = row >> 4, mr = row & 15;
            float f[4] = {av[i].x, av[i].y, av[i].z, av[i].w};
#pragma unroll
            for (int j = 0; j < 4; j++) {
                int kc = kc0 + j;
                int kblk = kc >> 3, kin = kc & 7;
                int t = ((mr & 7) << 2) | (kin & 3);
                int slot = ((kin >> 2) << 1) | (mr >> 3);
                sA[buf][(((kblk << 3) | mblk) << 7) + (t << 2) + slot] = f2tf32(f[j]);
            }
        }
#pragma unroll
        for (int i = 0; i < 2; i++) {
            int v = tid + 256 * i;
            int row = v >> 4;
            int nc0 = (v & 15) * 4;
            int kblk = row >> 3, kin = row & 7;
            float f[4] = {bv[i].x, bv[i].y, bv[i].z, bv[i].w};
#pragma unroll
            for (int j = 0; j < 4; j++) {
                int nc = nc0 + j;
                int nblk = nc >> 3, nin = nc & 7;
                int t = (nin << 2) | (kin & 3);
                int slot = kin >> 2;
                sB[buf][(((kblk << 3) | nblk) << 6) + (t << 1) + slot] = f2tf32(f[j]);
            }
        }
    };

    auto compute = [&](int buf) {
#pragma unroll
        for (int ks = 0; ks < 4; ks++) {
            uint32_t afr[2][4];
            uint32_t bfr[4][2];
#pragma unroll
            for (int mi = 0; mi < 2; mi++) {
                uint4 a = *(const uint4*)&sA[buf][(((ks << 3) | (wmb + mi)) << 7) + (lane << 2)];
                afr[mi][0] = a.x; afr[mi][1] = a.y; afr[mi][2] = a.z; afr[mi][3] = a.w;
            }
#pragma unroll
            for (int ni = 0; ni < 4; ni++) {
                uint2 b = *(const uint2*)&sB[buf][(((ks << 3) | (wnb + ni)) << 6) + (lane << 1)];
                bfr[ni][0] = b.x; bfr[ni][1] = b.y;
            }
#pragma unroll
            for (int mi = 0; mi < 2; mi++)
#pragma unroll
                for (int ni = 0; ni < 4; ni++)
                    mma_tf32(acc[mi][ni], afr[mi], bfr[ni]);
        }
    };

    ldg_tile(0);
    sts_tile(0);
    __syncthreads();
#pragma unroll
    for (int kt = 0; kt < KT; kt++) {
        if (kt + 1 < KT) ldg_tile(kt + 1);
        compute(kt & 1);
        if (kt + 1 < KT) sts_tile((kt + 1) & 1);
        __syncthreads();
    }

    const int g = lane >> 2;
    const int cq = lane & 3;
#pragma unroll
    for (int ni = 0; ni < 4; ni++) {
        int gn = n0 + ((wnb + ni) << 3) + cq * 2;
        float bx = g_bias[gn];
        float by = g_bias[gn + 1];
#pragma unroll
        for (int mi = 0; mi < 2; mi++) {
            int gm = m0 + ((wmb + mi) << 4) + g;
            float2 r0 = make_float2(acc[mi][ni][0] + bx, acc[mi][ni][1] + by);
            float2 r1 = make_float2(acc[mi][ni][2] + bx, acc[mi][ni][3] + by);
            *(float2*)(g_gx + (size_t)gm * GG + gn) = r0;
            *(float2*)(g_gx + (size_t)(gm + 8) * GG + gn) = r1;
        }
    }
}

// ---------------------------------------------------------------------------
// Recurrent scan (tensor cores). MB=16 batch rows per CTA -> 32 CTAs.
// Per step: gates[16][1024] = gx[b,t] + h[16,256] @ WhhP, via m16n8k8 tf32 mma.
// Warp w owns gate columns [w*128, w*128+128) = nblk w*16..w*16+15.
// h kept in SMEM in A-fragment order; W streamed from L2 in B-fragment order
// (1 LDG.128 = fragments for 2 k-blocks). Elementwise update in fp32,
// c state in registers (thread tid owns h column tid, all 16 rows).
// ---------------------------------------------------------------------------
__global__ __launch_bounds__(256, 1)
void lstm_scan_mma(float* __restrict__ out_in)
{
    float* out = out_in ? out_in : (float*)g_out1;

    extern __shared__ float smem[];
    float* gxb = smem;                                  // [16][GXS] gx/gates buffer
    uint32_t* shA = (uint32_t*)(smem + 16 * GXS);       // [32 kblk][32 lane][4 slot] tf32 h

    const int tid  = threadIdx.x;
    const int warp = tid >> 5;
    const int lane = tid & 31;
    const int b0 = blockIdx.x * 16;
    const int g  = lane >> 2;
    const int cq = lane & 3;

    // init: h = 0, c = 0
    for (int i = tid; i < 32 * 32 * 4; i += 256) shA[i] = 0u;
    float cst[16];
#pragma unroll
    for (int m = 0; m < 16; m++) cst[m] = 0.f;
    __syncthreads();

    const uint4* __restrict__ Wp = (const uint4*)g_WhhP;  // [(nblk*16+kpair)*32 + lane]
    const uint4* wwarp = Wp + (size_t)warp * 16 * 16 * 32 + lane;

    for (int t = 0; t < TT; t++) {
        // ---- phase 1: stage gx rows into SMEM (coalesced) ----
#pragma unroll
        for (int r = 0; r < 2; r++) {
            int m = warp * 2 + r;
            const float4* src = (const float4*)(g_gx + ((size_t)(b0 + m) * TT + t) * GG);
            float4* dst = (float4*)(gxb + m * GXS);
#pragma unroll
            for (int i = 0; i < 8; i++)
                dst[i * 32 + lane] = src[i * 32 + lane];
        }
        __syncthreads();

        // ---- phase 2: mma. acc initialized from gx. ----
        float acc[16][4];
#pragma unroll
        for (int nb = 0; nb < 16; nb++) {
            int n = (warp * 16 + nb) * 8 + cq * 2;
            float2 lo = *(const float2*)(gxb + g * GXS + n);
            float2 hi = *(const float2*)(gxb + (g + 8) * GXS + n);
            acc[nb][0] = lo.x; acc[nb][1] = lo.y; acc[nb][2] = hi.x; acc[nb][3] = hi.y;
        }

#pragma unroll 4
        for (int kp = 0; kp < 16; kp++) {
            uint4 a0v = *(const uint4*)&shA[((2 * kp) * 32 + lane) * 4];
            uint4 a1v = *(const uint4*)&shA[((2 * kp + 1) * 32 + lane) * 4];
            uint32_t a0[4] = {a0v.x, a0v.y, a0v.z, a0v.w};
            uint32_t a1[4] = {a1v.x, a1v.y, a1v.z, a1v.w};
#pragma unroll
            for (int nb = 0; nb < 16; nb++) {
                uint4 w = wwarp[(nb * 16 + kp) * 32];
                uint32_t blo[2] = {w.x, w.y};
                uint32_t bhi[2] = {w.z, w.w};
                mma_tf32(acc[nb], a0, blo);
                mma_tf32(acc[nb], a1, bhi);
            }
        }

        // ---- phase 3: write gates back to SMEM (own slice, warp-local order ok) ----
#pragma unroll
        for (int nb = 0; nb < 16; nb++) {
            int n = (warp * 16 + nb) * 8 + cq * 2;
            *(float2*)(gxb + g * GXS + n) = make_float2(acc[nb][0], acc[nb][1]);
            *(float2*)(gxb + (g + 8) * GXS + n) = make_float2(acc[nb][2], acc[nb][3]);
        }
        __syncthreads();

        // ---- phase 4: elementwise LSTM update. Thread tid owns h column tid. ----
        {
            const int kblk = tid >> 3, kin = tid & 7;
            const int laneBase = kin & 3;
            const int slotBase = (kin >> 2) << 1;
#pragma unroll
            for (int m = 0; m < 16; m++) {
                float4 gv = *(const float4*)(gxb + m * GXS + tid * 4);
                float ig = 1.f / (1.f + __expf(-gv.x));
                float fg = 1.f / (1.f + __expf(-gv.y));
                float gg = tanhf(gv.z);
                float og = 1.f / (1.f + __expf(-gv.w));
                float cn = fg * cst[m] + ig * gg;
                cst[m] = cn;
                float h = og * tanhf(cn);
                out[((size_t)(b0 + m) * TT + t) * HH + tid] = h;
                int laneA = ((m & 7) << 2) | laneBase;
                int slot  = slotBase | (m >> 3);
                shA[(kblk * 32 + laneA) * 4 + slot] = f2tf32(h);
            }
        }
        __syncthreads();
    }
}

// ---------------------------------------------------------------------------
// Launch
// ---------------------------------------------------------------------------
extern "C" void kernel_launch(void* const* d_in, const int* in_sizes, int n_in,
                              void* d_out, int out_size)
{
    const float* x     = (const float*)d_in[0];
    const float* W_ih1 = (const float*)d_in[1];
    const float* W_hh1 = (const float*)d_in[2];
    const float* b_ih1 = (const float*)d_in[3];
    const float* b_hh1 = (const float*)d_in[4];
    const float* W_ih2 = (const float*)d_in[5];
    const float* W_hh2 = (const float*)d_in[6];
    const float* b_ih2 = (const float*)d_in[7];
    const float* b_hh2 = (const float*)d_in[8];
    float* out = (float*)d_out;

    const int scan_smem = (16 * GXS) * 4 + 32 * 32 * 4 * 4;  // 82432 bytes
    cudaFuncSetAttribute(lstm_scan_mma, cudaFuncAttributeMaxDynamicSharedMemorySize, scan_smem);

    dim3 ggrid(BT / 128, GG / 64);  // 672 x 16

    // Layer 1
    prep_weights<<<1024, 256>>>(W_ih1, W_hh1, b_ih1, b_hh1, II);
    gemm_gx_tf32<II><<<ggrid, 256>>>(x);
    lstm_scan_mma<<<BB / 16, 256, scan_smem>>>(nullptr);      // writes g_out1

    // Layer 2
    prep_weights<<<1024, 256>>>(W_ih2, W_hh2, b_ih2, b_hh2, HH);
    gemm_gx_tf32<HH><<<ggrid, 256>>>(nullptr);                // reads g_out1
    lstm_scan_mma<<<BB / 16, 256, scan_smem>>>(out);          // writes final output
}